// round 1
// baseline (speedup 1.0000x reference)
#include <cuda_runtime.h>
#include <math.h>

// ---- problem dims ----
#define NB 48
#define NA 16
#define OBS 128
#define ACTD 32
#define HID 128
#define LL 768            // NB*NA  (MHA sequence length due to batch_first=False quirk)
#define LN 12288          // LL*NA  (rows of the RSA-block linears)
#define EMB 128
#define HEADS 4
#define HD 32
#define NP 64             // NA*HEADS independent attention problems
#define QKV_ROW 384
#define QKV_LSTRIDE (NA*QKV_ROW)   // 6144

// output layout in d_out (floats): policy_flat | q_values | eo
#define OUT_POLICY 0
#define OUT_Q      24576
#define OUT_EO     25344

// ---- scratch (__device__ globals: allocation-free rule) ----
__device__ __align__(256) float g_H1[LL * 256];
__device__ __align__(256) float g_H2[LL * HID];
__device__ __align__(256) float g_ea[LL * HID];
__device__ __align__(256) float g_cat[LL * 160];
__device__ __align__(256) float g_cf[(size_t)LN * EMB];
__device__ __align__(256) float g_x1[(size_t)LN * EMB];
__device__ __align__(256) float g_qkv[(size_t)LN * QKV_ROW];
__device__ __align__(256) float g_scores[(size_t)NP * LL * LL];   // ~151 MB
__device__ __align__(256) float g_ao[(size_t)LN * EMB];
__device__ __align__(256) float g_aop[(size_t)LN * EMB];
__device__ __align__(256) float g_ctx[(size_t)LN * EMB];

// ---- generic tiled SGEMM: C = act(A(MxK) @ W(NxK)^T + bias [+ Res]) ----
// BM=BN=64, BK=16, 256 threads, 4x4 microtile. M % 64 == 0, K % 16 == 0 required.
#define ACT_NONE 0
#define ACT_LEAKY 1
#define ACT_GELU 2
#define ACT_RELU 3

template <int ACTI>
__global__ void __launch_bounds__(256)
gemm_kernel(const float* __restrict__ A, const float* __restrict__ W,
            const float* __restrict__ bias, const float* __restrict__ Res,
            float* __restrict__ C, int M, int N, int K)
{
    __shared__ __align__(16) float As[16][64];
    __shared__ __align__(16) float Ws[16][64];

    const int tid = threadIdx.x;
    const int tx = tid & 15;          // n micro
    const int ty = tid >> 4;          // m micro
    const int m0 = blockIdx.y * 64;
    const int n0 = blockIdx.x * 64;

    const int lr = tid >> 2;          // 0..63 row in tile
    const int lc = (tid & 3) * 4;     // 0,4,8,12 k in tile

    float acc[4][4];
#pragma unroll
    for (int i = 0; i < 4; i++)
#pragma unroll
        for (int j = 0; j < 4; j++) acc[i][j] = 0.f;

    for (int k0 = 0; k0 < K; k0 += 16) {
        float4 av = *(const float4*)(A + (size_t)(m0 + lr) * K + k0 + lc);
        As[lc + 0][lr] = av.x; As[lc + 1][lr] = av.y;
        As[lc + 2][lr] = av.z; As[lc + 3][lr] = av.w;

        float4 wv = make_float4(0.f, 0.f, 0.f, 0.f);
        if (n0 + lr < N)
            wv = *(const float4*)(W + (size_t)(n0 + lr) * K + k0 + lc);
        Ws[lc + 0][lr] = wv.x; Ws[lc + 1][lr] = wv.y;
        Ws[lc + 2][lr] = wv.z; Ws[lc + 3][lr] = wv.w;

        __syncthreads();
#pragma unroll
        for (int kk = 0; kk < 16; kk++) {
            float4 a = *(const float4*)&As[kk][ty * 4];
            float4 b = *(const float4*)&Ws[kk][tx * 4];
            acc[0][0] += a.x * b.x; acc[0][1] += a.x * b.y; acc[0][2] += a.x * b.z; acc[0][3] += a.x * b.w;
            acc[1][0] += a.y * b.x; acc[1][1] += a.y * b.y; acc[1][2] += a.y * b.z; acc[1][3] += a.y * b.w;
            acc[2][0] += a.z * b.x; acc[2][1] += a.z * b.y; acc[2][2] += a.z * b.z; acc[2][3] += a.z * b.w;
            acc[3][0] += a.w * b.x; acc[3][1] += a.w * b.y; acc[3][2] += a.w * b.z; acc[3][3] += a.w * b.w;
        }
        __syncthreads();
    }

#pragma unroll
    for (int i = 0; i < 4; i++) {
        const int m = m0 + ty * 4 + i;
#pragma unroll
        for (int j = 0; j < 4; j++) {
            const int n = n0 + tx * 4 + j;
            if (n < N) {
                float v = acc[i][j] + bias[n];
                if (Res) v += Res[(size_t)m * N + n];
                if (ACTI == ACT_LEAKY) v = (v > 0.f) ? v : 0.01f * v;
                else if (ACTI == ACT_GELU) v = 0.5f * v * (1.0f + erff(v * 0.70710678118654752f));
                else if (ACTI == ACT_RELU) v = fmaxf(v, 0.f);
                C[(size_t)m * N + n] = v;
            }
        }
    }
}

// ---- concat [obs | policy] -> g_cat (LL x 160) ----
__global__ void cat_kernel(const float* __restrict__ obs, const float* __restrict__ policy,
                           float* __restrict__ cat)
{
    const int l = blockIdx.x;
    const int t = threadIdx.x;   // 160 threads
    cat[(size_t)l * 160 + t] = (t < 128) ? obs[(size_t)l * 128 + t]
                                         : policy[(size_t)l * 32 + (t - 128)];
}

// ---- counterfactual gather: cf row r = (l*16 + k) ----
__global__ void cf_kernel(const float* __restrict__ eo, const float* __restrict__ ea,
                          float* __restrict__ cf)
{
    const int r = blockIdx.x;          // 0..LN-1
    const int k = r & 15;
    const int l = r >> 4;              // l = b*16+i
    const int i = l & 15;
    const int b = l >> 4;
    const float* src;
    if (k == 0) src = eo + (size_t)l * EMB;
    else {
        const int j = (k - 1 < i) ? (k - 1) : k;
        src = ea + (size_t)(b * 16 + j) * EMB;
    }
    cf[(size_t)r * EMB + threadIdx.x] = src[threadIdx.x];
}

// ---- QK^T: scores[p][l][m] = Q.K / sqrt(32) ----
__global__ void __launch_bounds__(256)
qk_kernel(const float* __restrict__ qkv, float* __restrict__ scores)
{
    const int p = blockIdx.z;
    const int n = p >> 2, h = p & 3;
    const float* Qb = qkv + n * QKV_ROW + h * HD;
    const float* Kb = Qb + 128;

    __shared__ __align__(16) float Qs[32][64];   // [d][l]
    __shared__ __align__(16) float Ks[32][64];   // [d][m]

    const int tid = threadIdx.x;
    const int lr = tid >> 2;
    const int lc = (tid & 3) * 8;
    const int l0 = blockIdx.y * 64;
    const int m0 = blockIdx.x * 64;

    {
        const float* s = Qb + (size_t)(l0 + lr) * QKV_LSTRIDE + lc;
        float4 v0 = ((const float4*)s)[0], v1 = ((const float4*)s)[1];
        Qs[lc + 0][lr] = v0.x; Qs[lc + 1][lr] = v0.y; Qs[lc + 2][lr] = v0.z; Qs[lc + 3][lr] = v0.w;
        Qs[lc + 4][lr] = v1.x; Qs[lc + 5][lr] = v1.y; Qs[lc + 6][lr] = v1.z; Qs[lc + 7][lr] = v1.w;
        const float* t = Kb + (size_t)(m0 + lr) * QKV_LSTRIDE + lc;
        float4 w0 = ((const float4*)t)[0], w1 = ((const float4*)t)[1];
        Ks[lc + 0][lr] = w0.x; Ks[lc + 1][lr] = w0.y; Ks[lc + 2][lr] = w0.z; Ks[lc + 3][lr] = w0.w;
        Ks[lc + 4][lr] = w1.x; Ks[lc + 5][lr] = w1.y; Ks[lc + 6][lr] = w1.z; Ks[lc + 7][lr] = w1.w;
    }
    __syncthreads();

    const int tx = tid & 15, ty = tid >> 4;
    float acc[4][4];
#pragma unroll
    for (int i = 0; i < 4; i++)
#pragma unroll
        for (int j = 0; j < 4; j++) acc[i][j] = 0.f;

#pragma unroll
    for (int d = 0; d < 32; d++) {
        float4 a = *(const float4*)&Qs[d][ty * 4];
        float4 b = *(const float4*)&Ks[d][tx * 4];
        acc[0][0] += a.x * b.x; acc[0][1] += a.x * b.y; acc[0][2] += a.x * b.z; acc[0][3] += a.x * b.w;
        acc[1][0] += a.y * b.x; acc[1][1] += a.y * b.y; acc[1][2] += a.y * b.z; acc[1][3] += a.y * b.w;
        acc[2][0] += a.z * b.x; acc[2][1] += a.z * b.y; acc[2][2] += a.z * b.z; acc[2][3] += a.z * b.w;
        acc[3][0] += a.w * b.x; acc[3][1] += a.w * b.y; acc[3][2] += a.w * b.z; acc[3][3] += a.w * b.w;
    }

    const float sc = 0.17677669529663687f;   // 1/sqrt(32)
    float* out = scores + ((size_t)p * LL + l0) * LL + m0;
#pragma unroll
    for (int i = 0; i < 4; i++)
#pragma unroll
        for (int j = 0; j < 4; j++)
            out[(size_t)(ty * 4 + i) * LL + tx * 4 + j] = acc[i][j] * sc;
}

// ---- softmax over m, in place ----
__global__ void __launch_bounds__(256)
softmax_kernel(float* __restrict__ scores)
{
    const int p = blockIdx.y, l = blockIdx.x;
    float* row = scores + ((size_t)p * LL + l) * LL;
    __shared__ float red[256];
    const int tid = threadIdx.x;

    float mx = -1e30f;
    for (int i = tid; i < LL; i += 256) mx = fmaxf(mx, row[i]);
    red[tid] = mx; __syncthreads();
    for (int s = 128; s > 0; s >>= 1) { if (tid < s) red[tid] = fmaxf(red[tid], red[tid + s]); __syncthreads(); }
    mx = red[0]; __syncthreads();

    float sum = 0.f;
    for (int i = tid; i < LL; i += 256) { float e = __expf(row[i] - mx); row[i] = e; sum += e; }
    red[tid] = sum; __syncthreads();
    for (int s = 128; s > 0; s >>= 1) { if (tid < s) red[tid] += red[tid + s]; __syncthreads(); }
    const float inv = 1.0f / red[0];
    __syncthreads();
    for (int i = tid; i < LL; i += 256) row[i] *= inv;
}

// ---- AV: ao[(l*16+n)*128 + h*32 + d] = sum_m attn[p][l][m] * V[m][d] ----
__global__ void __launch_bounds__(256)
av_kernel(const float* __restrict__ scores, const float* __restrict__ qkv,
          float* __restrict__ ao)
{
    const int p = blockIdx.y;
    const int n = p >> 2, h = p & 3;
    const int l0 = blockIdx.x * 64;
    const float* Vb = qkv + n * QKV_ROW + h * HD + 256;

    __shared__ __align__(16) float As[64][64];   // attn [l][m]
    __shared__ __align__(16) float Vs[64][32];   // V [m][d]

    const int tid = threadIdx.x;
    const int tx = tid & 31;      // d
    const int ty = tid >> 5;      // 0..7 -> l-group (warp id)
    float acc[8];
#pragma unroll
    for (int i = 0; i < 8; i++) acc[i] = 0.f;

    const int lr = tid >> 2;          // 0..63
    const int lcA = (tid & 3) * 16;   // attn cols
    const int lcV = (tid & 3) * 8;    // v cols

    for (int m0 = 0; m0 < LL; m0 += 64) {
        const float* src = scores + ((size_t)p * LL + l0 + lr) * LL + m0 + lcA;
        float4* dst = (float4*)&As[lr][lcA];
        dst[0] = ((const float4*)src)[0]; dst[1] = ((const float4*)src)[1];
        dst[2] = ((const float4*)src)[2]; dst[3] = ((const float4*)src)[3];

        const float* vsrc = Vb + (size_t)(m0 + lr) * QKV_LSTRIDE + lcV;
        *(float4*)&Vs[lr][lcV]     = ((const float4*)vsrc)[0];
        *(float4*)&Vs[lr][lcV + 4] = ((const float4*)vsrc)[1];
        __syncthreads();

#pragma unroll
        for (int mm = 0; mm < 64; mm += 4) {
            const float v0 = Vs[mm + 0][tx];
            const float v1 = Vs[mm + 1][tx];
            const float v2 = Vs[mm + 2][tx];
            const float v3 = Vs[mm + 3][tx];
#pragma unroll
            for (int i = 0; i < 8; i++) {
                float4 a = *(const float4*)&As[ty * 8 + i][mm];
                acc[i] += a.x * v0 + a.y * v1 + a.z * v2 + a.w * v3;
            }
        }
        __syncthreads();
    }

#pragma unroll
    for (int i = 0; i < 8; i++) {
        const int l = l0 + ty * 8 + i;
        ao[((size_t)l * NA + n) * EMB + h * HD + tx] = acc[i];
    }
}

// ---- q head: q_values[l] = sum_k (ctx[l,k,:].qw) + 16*qb ----
__global__ void __launch_bounds__(256)
qv_kernel(const float* __restrict__ ctx, const float* __restrict__ qw,
          const float* __restrict__ qb, float* __restrict__ qout)
{
    const int l = blockIdx.x, tid = threadIdx.x;
    const float* base = ctx + (size_t)l * NA * EMB;
    float s = 0.f;
    for (int i = tid; i < NA * EMB; i += 256) s += base[i] * qw[i & 127];
    __shared__ float red[256];
    red[tid] = s; __syncthreads();
    for (int st = 128; st > 0; st >>= 1) { if (tid < st) red[tid] += red[tid + st]; __syncthreads(); }
    if (tid == 0) qout[l] = red[0] + 16.0f * qb[0];
}

extern "C" void kernel_launch(void* const* d_in, const int* in_sizes, int n_in,
                              void* d_out, int out_size)
{
    const float* obs = (const float*)d_in[0];
    const float* aw1 = (const float*)d_in[1];  const float* ab1 = (const float*)d_in[2];
    const float* aw2 = (const float*)d_in[3];  const float* ab2 = (const float*)d_in[4];
    const float* aw3 = (const float*)d_in[5];  const float* ab3 = (const float*)d_in[6];
    const float* eow = (const float*)d_in[7];  const float* eob = (const float*)d_in[8];
    const float* eaw = (const float*)d_in[9];  const float* eab = (const float*)d_in[10];
    const float* riw = (const float*)d_in[11]; const float* rib = (const float*)d_in[12];
    const float* roww = (const float*)d_in[13]; const float* rob = (const float*)d_in[14];
    const float* miw = (const float*)d_in[15]; const float* mib = (const float*)d_in[16];
    const float* mow = (const float*)d_in[17]; const float* mob = (const float*)d_in[18];
    const float* qw  = (const float*)d_in[19]; const float* qb  = (const float*)d_in[20];

    float* out = (float*)d_out;
    float* out_policy = out + OUT_POLICY;
    float* out_q      = out + OUT_Q;
    float* out_eo     = out + OUT_EO;

    float* H1 = nullptr, *H2 = nullptr, *ea = nullptr, *cat = nullptr, *cf = nullptr,
         *x1 = nullptr, *qkv = nullptr, *scores = nullptr, *ao = nullptr, *aop = nullptr,
         *ctx = nullptr;
    cudaGetSymbolAddress((void**)&H1, g_H1);
    cudaGetSymbolAddress((void**)&H2, g_H2);
    cudaGetSymbolAddress((void**)&ea, g_ea);
    cudaGetSymbolAddress((void**)&cat, g_cat);
    cudaGetSymbolAddress((void**)&cf, g_cf);
    cudaGetSymbolAddress((void**)&x1, g_x1);
    cudaGetSymbolAddress((void**)&qkv, g_qkv);
    cudaGetSymbolAddress((void**)&scores, g_scores);
    cudaGetSymbolAddress((void**)&ao, g_ao);
    cudaGetSymbolAddress((void**)&aop, g_aop);
    cudaGetSymbolAddress((void**)&ctx, g_ctx);

    dim3 blk(256);

    // Actor
    gemm_kernel<ACT_LEAKY><<<dim3(4, 12), blk>>>(obs, aw1, ab1, nullptr, H1, LL, 256, 128);
    gemm_kernel<ACT_LEAKY><<<dim3(2, 12), blk>>>(H1, aw2, ab2, nullptr, H2, LL, 128, 256);
    gemm_kernel<ACT_GELU ><<<dim3(1, 12), blk>>>(H2, aw3, ab3, nullptr, out_policy, LL, 32, 128);

    // State encoder
    gemm_kernel<ACT_NONE ><<<dim3(2, 12), blk>>>(obs, eow, eob, nullptr, out_eo, LL, 128, 128);
    cat_kernel<<<LL, 160>>>(obs, out_policy, cat);
    gemm_kernel<ACT_NONE ><<<dim3(2, 12), blk>>>(cat, eaw, eab, nullptr, ea, LL, 128, 160);

    // Counterfactual gather + RSA input
    cf_kernel<<<LN, 128>>>(out_eo, ea, cf);
    gemm_kernel<ACT_RELU ><<<dim3(2, 192), blk>>>(cf, riw, rib, nullptr, x1, LN, 128, 128);
    gemm_kernel<ACT_NONE ><<<dim3(6, 192), blk>>>(x1, miw, mib, nullptr, qkv, LN, 384, 128);

    // Attention (64 problems, seq 768, hd 32)
    qk_kernel<<<dim3(12, 12, NP), blk>>>(qkv, scores);
    softmax_kernel<<<dim3(LL, NP), blk>>>(scores);
    av_kernel<<<dim3(12, NP), blk>>>(scores, qkv, ao);

    // out_proj (+ residual fused), output layer, q head
    gemm_kernel<ACT_NONE ><<<dim3(2, 192), blk>>>(ao, mow, mob, x1, aop, LN, 128, 128);
    gemm_kernel<ACT_RELU ><<<dim3(2, 192), blk>>>(aop, roww, rob, nullptr, ctx, LN, 128, 128);
    qv_kernel<<<LL, blk>>>(ctx, qw, qb, out_q);

    (void)in_sizes; (void)n_in; (void)out_size;
}

// round 2
// speedup vs baseline: 1.6095x; 1.6095x over previous
#include <cuda_runtime.h>
#include <math.h>

// ---- problem dims ----
#define NB 48
#define NA 16
#define LL 768            // NB*NA  (MHA sequence length)
#define LN 12288          // LL*NA
#define EMB 128
#define QKV_ROW 384
#define QKV_LSTRIDE 6144  // NA*QKV_ROW
#define HD 32
#define NP 64             // NA*HEADS attention problems

// output layout in d_out (floats): policy_flat | q_values | eo
#define OUT_POLICY 0
#define OUT_Q      24576
#define OUT_EO     25344

// ---- scratch ----
__device__ __align__(256) float g_H1[LL * 256];
__device__ __align__(256) float g_H2[LL * 128];
__device__ __align__(256) float g_ea[LL * 128];
__device__ __align__(256) float g_cat[LL * 160];
__device__ __align__(256) float g_x1[(size_t)LN * 128];
__device__ __align__(256) float g_qkv[(size_t)LN * 384];
__device__ __align__(256) float g_ao[(size_t)LN * 128];
__device__ __align__(256) float g_aop[(size_t)LN * 128];
__device__ __align__(256) float g_ctx[(size_t)LN * 128];

#define ACT_NONE 0
#define ACT_LEAKY 1
#define ACT_GELU 2
#define ACT_RELU 3

// ============================================================================
// gemm64: proven round-1 kernel for small (768-row) GEMMs. 64x64x16, 4x4 micro.
// ============================================================================
template <int ACTI>
__global__ void __launch_bounds__(256)
gemm64(const float* __restrict__ A, const float* __restrict__ W,
       const float* __restrict__ bias, const float* __restrict__ Res,
       float* __restrict__ C, int M, int N, int K)
{
    __shared__ __align__(16) float As[16][64];
    __shared__ __align__(16) float Ws[16][64];

    const int tid = threadIdx.x;
    const int tx = tid & 15;
    const int ty = tid >> 4;
    const int m0 = blockIdx.y * 64;
    const int n0 = blockIdx.x * 64;

    const int lr = tid >> 2;
    const int lc = (tid & 3) * 4;

    float acc[4][4];
#pragma unroll
    for (int i = 0; i < 4; i++)
#pragma unroll
        for (int j = 0; j < 4; j++) acc[i][j] = 0.f;

    for (int k0 = 0; k0 < K; k0 += 16) {
        float4 av = *(const float4*)(A + (size_t)(m0 + lr) * K + k0 + lc);
        As[lc + 0][lr] = av.x; As[lc + 1][lr] = av.y;
        As[lc + 2][lr] = av.z; As[lc + 3][lr] = av.w;

        float4 wv = make_float4(0.f, 0.f, 0.f, 0.f);
        if (n0 + lr < N)
            wv = *(const float4*)(W + (size_t)(n0 + lr) * K + k0 + lc);
        Ws[lc + 0][lr] = wv.x; Ws[lc + 1][lr] = wv.y;
        Ws[lc + 2][lr] = wv.z; Ws[lc + 3][lr] = wv.w;

        __syncthreads();
#pragma unroll
        for (int kk = 0; kk < 16; kk++) {
            float4 a = *(const float4*)&As[kk][ty * 4];
            float4 b = *(const float4*)&Ws[kk][tx * 4];
            acc[0][0] += a.x * b.x; acc[0][1] += a.x * b.y; acc[0][2] += a.x * b.z; acc[0][3] += a.x * b.w;
            acc[1][0] += a.y * b.x; acc[1][1] += a.y * b.y; acc[1][2] += a.y * b.z; acc[1][3] += a.y * b.w;
            acc[2][0] += a.z * b.x; acc[2][1] += a.z * b.y; acc[2][2] += a.z * b.z; acc[2][3] += a.z * b.w;
            acc[3][0] += a.w * b.x; acc[3][1] += a.w * b.y; acc[3][2] += a.w * b.z; acc[3][3] += a.w * b.w;
        }
        __syncthreads();
    }

#pragma unroll
    for (int i = 0; i < 4; i++) {
        const int m = m0 + ty * 4 + i;
#pragma unroll
        for (int j = 0; j < 4; j++) {
            const int n = n0 + tx * 4 + j;
            if (n < N) {
                float v = acc[i][j] + bias[n];
                if (Res) v += Res[(size_t)m * N + n];
                if (ACTI == ACT_LEAKY) v = (v > 0.f) ? v : 0.01f * v;
                else if (ACTI == ACT_GELU) v = 0.5f * v * (1.0f + erff(v * 0.70710678118654752f));
                else if (ACTI == ACT_RELU) v = fmaxf(v, 0.f);
                C[(size_t)m * N + n] = v;
            }
        }
    }
}

// ============================================================================
// gemm128: 128x128x8, 8x8 micro, double-buffered. Requires M%128==0, N%128==0,
// K%8==0. Optional A-row gather (counterfactual construction).
// ============================================================================
template <int ACTI, bool GATHER>
__global__ void __launch_bounds__(256)
gemm128(const float* __restrict__ A, const float* __restrict__ W,
        const float* __restrict__ bias, const float* __restrict__ Res,
        float* __restrict__ C, int M, int N, int K,
        const float* __restrict__ eo, const float* __restrict__ ea)
{
    __shared__ __align__(16) float As[2][8][132];
    __shared__ __align__(16) float Bs[2][8][132];

    const int tid = threadIdx.x;
    const int m0 = blockIdx.y * 128;
    const int n0 = blockIdx.x * 128;
    const int lr = tid >> 1;          // 0..127 row within tile
    const int lk = (tid & 1) * 4;     // 0 or 4

    const float* arow;
    if (GATHER) {
        int r = m0 + lr;
        int k = r & 15, l = r >> 4;
        int i = l & 15, b = l >> 4;
        if (k == 0) arow = eo + (size_t)l * 128;
        else {
            int j = (k - 1 < i) ? (k - 1) : k;
            arow = ea + (size_t)(b * 16 + j) * 128;
        }
    } else {
        arow = A + (size_t)(m0 + lr) * K;
    }
    const float* wrow = W + (size_t)(n0 + lr) * K;

    const int tx = tid & 15, ty = tid >> 4;
    float acc[8][8];
#pragma unroll
    for (int i = 0; i < 8; i++)
#pragma unroll
        for (int j = 0; j < 8; j++) acc[i][j] = 0.f;

    float4 a_pre = *(const float4*)(arow + lk);
    float4 b_pre = *(const float4*)(wrow + lk);
    As[0][lk + 0][lr] = a_pre.x; As[0][lk + 1][lr] = a_pre.y;
    As[0][lk + 2][lr] = a_pre.z; As[0][lk + 3][lr] = a_pre.w;
    Bs[0][lk + 0][lr] = b_pre.x; Bs[0][lk + 1][lr] = b_pre.y;
    Bs[0][lk + 2][lr] = b_pre.z; Bs[0][lk + 3][lr] = b_pre.w;
    __syncthreads();

    int buf = 0;
    for (int k0 = 0; k0 < K; k0 += 8) {
        const bool has_next = (k0 + 8 < K);
        if (has_next) {
            a_pre = *(const float4*)(arow + k0 + 8 + lk);
            b_pre = *(const float4*)(wrow + k0 + 8 + lk);
        }
#pragma unroll
        for (int kk = 0; kk < 8; kk++) {
            float a[8], b[8];
            *(float4*)&a[0] = *(const float4*)&As[buf][kk][ty * 8];
            *(float4*)&a[4] = *(const float4*)&As[buf][kk][ty * 8 + 4];
            *(float4*)&b[0] = *(const float4*)&Bs[buf][kk][tx * 8];
            *(float4*)&b[4] = *(const float4*)&Bs[buf][kk][tx * 8 + 4];
#pragma unroll
            for (int i = 0; i < 8; i++)
#pragma unroll
                for (int j = 0; j < 8; j++) acc[i][j] += a[i] * b[j];
        }
        if (has_next) {
            const int nb = buf ^ 1;
            As[nb][lk + 0][lr] = a_pre.x; As[nb][lk + 1][lr] = a_pre.y;
            As[nb][lk + 2][lr] = a_pre.z; As[nb][lk + 3][lr] = a_pre.w;
            Bs[nb][lk + 0][lr] = b_pre.x; Bs[nb][lk + 1][lr] = b_pre.y;
            Bs[nb][lk + 2][lr] = b_pre.z; Bs[nb][lk + 3][lr] = b_pre.w;
            __syncthreads();
            buf = nb;
        }
    }

    float bv[8];
    *(float4*)&bv[0] = *(const float4*)(bias + n0 + tx * 8);
    *(float4*)&bv[4] = *(const float4*)(bias + n0 + tx * 8 + 4);
#pragma unroll
    for (int i = 0; i < 8; i++) {
        const int m = m0 + ty * 8 + i;
        float out[8];
#pragma unroll
        for (int j = 0; j < 8; j++) {
            float v = acc[i][j] + bv[j];
            if (Res) v += Res[(size_t)m * N + n0 + tx * 8 + j];
            if (ACTI == ACT_LEAKY) v = (v > 0.f) ? v : 0.01f * v;
            else if (ACTI == ACT_GELU) v = 0.5f * v * (1.0f + erff(v * 0.70710678118654752f));
            else if (ACTI == ACT_RELU) v = fmaxf(v, 0.f);
            out[j] = v;
        }
        float* cp = C + (size_t)m * N + n0 + tx * 8;
        *(float4*)cp = *(float4*)&out[0];
        *(float4*)(cp + 4) = *(float4*)&out[4];
    }
}

// ============================================================================
// flash attention: one kernel per (problem p, 128-row l-tile). Online softmax.
// Eliminates the 151MB scores tensor entirely.
// ============================================================================
struct FlashSmem {
    float Qs[32][132];   // Q transposed [d][l]
    float Ks[32][68];    // K tile transposed [d][m]
    float Vs[64][32];    // V tile [m][d]
    float Ss[128][68];   // S tile row-major
    float Pt[64][132];   // P tile transposed [m][l]
    float Ms[128];
    float Lsum[128];
    float Cs[128];
};

__global__ void __launch_bounds__(256)
flash_kernel(const float* __restrict__ qkv, float* __restrict__ ao)
{
    extern __shared__ char smem_raw[];
    FlashSmem& sm = *reinterpret_cast<FlashSmem*>(smem_raw);

    const int p = blockIdx.y;
    const int n = p >> 2, h = p & 3;
    const int l0 = blockIdx.x * 128;
    const float* Qb = qkv + n * QKV_ROW + h * HD;
    const float* Kb = Qb + 128;
    const float* Vb = Qb + 256;

    const int tid = threadIdx.x;

    // load Q tile (128 x 32) transposed
#pragma unroll
    for (int t = 0; t < 4; t++) {
        const int f = tid + t * 256;          // 0..1023
        const int r = f >> 3, c = (f & 7) * 4;
        float4 v = *(const float4*)(Qb + (size_t)(l0 + r) * QKV_LSTRIDE + c);
        sm.Qs[c + 0][r] = v.x; sm.Qs[c + 1][r] = v.y;
        sm.Qs[c + 2][r] = v.z; sm.Qs[c + 3][r] = v.w;
    }
    if (tid < 128) { sm.Ms[tid] = -1e30f; sm.Lsum[tid] = 0.f; }

    float O[4][4];
#pragma unroll
    for (int i = 0; i < 4; i++)
#pragma unroll
        for (int j = 0; j < 4; j++) O[i][j] = 0.f;

    const int txA = tid & 15, tyA = tid >> 4;   // phase A: 8x4 micro (128x64)
    const int rB = tid >> 1, hB = tid & 1;      // phase B: 2 threads/row
    const int txC = tid & 7,  tyC = tid >> 3;   // phase C: 4x4 micro (128x32)

    for (int m0 = 0; m0 < LL; m0 += 64) {
        __syncthreads();     // protect Ks/Vs/Pt from previous-iter readers; Q ready
        // load K, V tiles (64 x 32)
#pragma unroll
        for (int t = 0; t < 2; t++) {
            const int f = tid + t * 256;       // 0..511
            const int r = f >> 3, c = (f & 7) * 4;
            float4 kv = *(const float4*)(Kb + (size_t)(m0 + r) * QKV_LSTRIDE + c);
            sm.Ks[c + 0][r] = kv.x; sm.Ks[c + 1][r] = kv.y;
            sm.Ks[c + 2][r] = kv.z; sm.Ks[c + 3][r] = kv.w;
            float4 vv = *(const float4*)(Vb + (size_t)(m0 + r) * QKV_LSTRIDE + c);
            *(float4*)&sm.Vs[r][c] = vv;
        }
        __syncthreads();

        // ---- phase A: S = Q.K^T * scale ----
        float fa[8][4];
#pragma unroll
        for (int i = 0; i < 8; i++)
#pragma unroll
            for (int j = 0; j < 4; j++) fa[i][j] = 0.f;
#pragma unroll 8
        for (int d = 0; d < 32; d++) {
            float a[8];
            *(float4*)&a[0] = *(const float4*)&sm.Qs[d][tyA * 8];
            *(float4*)&a[4] = *(const float4*)&sm.Qs[d][tyA * 8 + 4];
            float4 b = *(const float4*)&sm.Ks[d][txA * 4];
#pragma unroll
            for (int i = 0; i < 8; i++) {
                fa[i][0] += a[i] * b.x; fa[i][1] += a[i] * b.y;
                fa[i][2] += a[i] * b.z; fa[i][3] += a[i] * b.w;
            }
        }
        const float sc = 0.17677669529663687f;  // 1/sqrt(32)
#pragma unroll
        for (int i = 0; i < 8; i++)
#pragma unroll
            for (int j = 0; j < 4; j++)
                sm.Ss[tyA * 8 + i][txA * 4 + j] = fa[i][j] * sc;
        __syncthreads();

        // ---- phase B: online softmax stats + P (transposed) ----
        {
            const float* srow = &sm.Ss[rB][hB * 32];
            float mloc = -1e30f;
#pragma unroll 8
            for (int j = 0; j < 32; j++) mloc = fmaxf(mloc, srow[j]);
            float mo = __shfl_xor_sync(0xffffffffu, mloc, 1);
            float mt = fmaxf(mloc, mo);
            float m_old = sm.Ms[rB];
            float m_new = fmaxf(m_old, mt);
            float corr = __expf(m_old - m_new);
            float s = 0.f;
#pragma unroll 8
            for (int j = 0; j < 32; j++) {
                float e = __expf(srow[j] - m_new);
                sm.Pt[hB * 32 + j][rB] = e;
                s += e;
            }
            s += __shfl_xor_sync(0xffffffffu, s, 1);
            if (hB == 0) {
                sm.Ms[rB] = m_new;
                sm.Lsum[rB] = sm.Lsum[rB] * corr + s;
                sm.Cs[rB] = corr;
            }
        }
        __syncthreads();

        // ---- phase C: O = O*corr + P.V ----
        float cc[4];
#pragma unroll
        for (int i = 0; i < 4; i++) cc[i] = sm.Cs[tyC * 4 + i];
#pragma unroll
        for (int i = 0; i < 4; i++)
#pragma unroll
            for (int j = 0; j < 4; j++) O[i][j] *= cc[i];
#pragma unroll 8
        for (int mm = 0; mm < 64; mm++) {
            float4 a = *(const float4*)&sm.Pt[mm][tyC * 4];
            float4 b = *(const float4*)&sm.Vs[mm][txC * 4];
            O[0][0] += a.x * b.x; O[0][1] += a.x * b.y; O[0][2] += a.x * b.z; O[0][3] += a.x * b.w;
            O[1][0] += a.y * b.x; O[1][1] += a.y * b.y; O[1][2] += a.y * b.z; O[1][3] += a.y * b.w;
            O[2][0] += a.z * b.x; O[2][1] += a.z * b.y; O[2][2] += a.z * b.z; O[2][3] += a.z * b.w;
            O[3][0] += a.w * b.x; O[3][1] += a.w * b.y; O[3][2] += a.w * b.z; O[3][3] += a.w * b.w;
        }
    }

    // epilogue: normalize and write  (Lsum final: visible since last sync before phase C)
#pragma unroll
    for (int i = 0; i < 4; i++) {
        const float inv = 1.0f / sm.Lsum[tyC * 4 + i];
        const int l = l0 + tyC * 4 + i;
        float out[4];
#pragma unroll
        for (int j = 0; j < 4; j++) out[j] = O[i][j] * inv;
        *(float4*)(ao + ((size_t)l * NA + n) * EMB + h * HD + txC * 4) = *(float4*)&out[0];
    }
}

// ---- concat [obs | policy] -> g_cat (LL x 160) ----
__global__ void cat_kernel(const float* __restrict__ obs, const float* __restrict__ policy,
                           float* __restrict__ cat)
{
    const int l = blockIdx.x;
    const int t = threadIdx.x;
    cat[(size_t)l * 160 + t] = (t < 128) ? obs[(size_t)l * 128 + t]
                                         : policy[(size_t)l * 32 + (t - 128)];
}

// ---- q head ----
__global__ void __launch_bounds__(256)
qv_kernel(const float* __restrict__ ctx, const float* __restrict__ qw,
          const float* __restrict__ qb, float* __restrict__ qout)
{
    const int l = blockIdx.x, tid = threadIdx.x;
    const float* base = ctx + (size_t)l * NA * EMB;
    float s = 0.f;
    for (int i = tid; i < NA * EMB; i += 256) s += base[i] * qw[i & 127];
    __shared__ float red[256];
    red[tid] = s; __syncthreads();
    for (int st = 128; st > 0; st >>= 1) { if (tid < st) red[tid] += red[tid + st]; __syncthreads(); }
    if (tid == 0) qout[l] = red[0] + 16.0f * qb[0];
}

extern "C" void kernel_launch(void* const* d_in, const int* in_sizes, int n_in,
                              void* d_out, int out_size)
{
    const float* obs = (const float*)d_in[0];
    const float* aw1 = (const float*)d_in[1];  const float* ab1 = (const float*)d_in[2];
    const float* aw2 = (const float*)d_in[3];  const float* ab2 = (const float*)d_in[4];
    const float* aw3 = (const float*)d_in[5];  const float* ab3 = (const float*)d_in[6];
    const float* eow = (const float*)d_in[7];  const float* eob = (const float*)d_in[8];
    const float* eaw = (const float*)d_in[9];  const float* eab = (const float*)d_in[10];
    const float* riw = (const float*)d_in[11]; const float* rib = (const float*)d_in[12];
    const float* roww = (const float*)d_in[13]; const float* rob = (const float*)d_in[14];
    const float* miw = (const float*)d_in[15]; const float* mib = (const float*)d_in[16];
    const float* mow = (const float*)d_in[17]; const float* mob = (const float*)d_in[18];
    const float* qw  = (const float*)d_in[19]; const float* qb  = (const float*)d_in[20];

    float* out = (float*)d_out;
    float* out_policy = out + OUT_POLICY;
    float* out_q      = out + OUT_Q;
    float* out_eo     = out + OUT_EO;

    float *H1 = nullptr, *H2 = nullptr, *ea = nullptr, *cat = nullptr,
          *x1 = nullptr, *qkvb = nullptr, *ao = nullptr, *aop = nullptr, *ctx = nullptr;
    cudaGetSymbolAddress((void**)&H1, g_H1);
    cudaGetSymbolAddress((void**)&H2, g_H2);
    cudaGetSymbolAddress((void**)&ea, g_ea);
    cudaGetSymbolAddress((void**)&cat, g_cat);
    cudaGetSymbolAddress((void**)&x1, g_x1);
    cudaGetSymbolAddress((void**)&qkvb, g_qkv);
    cudaGetSymbolAddress((void**)&ao, g_ao);
    cudaGetSymbolAddress((void**)&aop, g_aop);
    cudaGetSymbolAddress((void**)&ctx, g_ctx);

    cudaFuncSetAttribute(flash_kernel, cudaFuncAttributeMaxDynamicSharedMemorySize,
                         (int)sizeof(FlashSmem));

    dim3 blk(256);

    // Actor (small M -> gemm64 for parallelism)
    gemm64<ACT_LEAKY><<<dim3(4, 12), blk>>>(obs, aw1, ab1, nullptr, H1, LL, 256, 128);
    gemm64<ACT_LEAKY><<<dim3(2, 12), blk>>>(H1, aw2, ab2, nullptr, H2, LL, 128, 256);
    gemm64<ACT_GELU ><<<dim3(1, 12), blk>>>(H2, aw3, ab3, nullptr, out_policy, LL, 32, 128);

    // State encoder
    gemm64<ACT_NONE ><<<dim3(2, 12), blk>>>(obs, eow, eob, nullptr, out_eo, LL, 128, 128);
    cat_kernel<<<LL, 160>>>(obs, out_policy, cat);
    gemm64<ACT_NONE ><<<dim3(2, 12), blk>>>(cat, eaw, eab, nullptr, ea, LL, 128, 160);

    // RSA block input (gather fused) + in_proj
    gemm128<ACT_RELU, true ><<<dim3(1, 96), blk>>>(nullptr, riw, rib, nullptr, x1,
                                                   LN, 128, 128, out_eo, ea);
    gemm128<ACT_NONE, false><<<dim3(3, 96), blk>>>(x1, miw, mib, nullptr, qkvb,
                                                   LN, 384, 128, nullptr, nullptr);

    // fused flash attention (64 problems x 6 l-tiles)
    flash_kernel<<<dim3(6, NP), blk, sizeof(FlashSmem)>>>(qkvb, ao);

    // out_proj (+residual), output layer, q head
    gemm128<ACT_NONE, false><<<dim3(1, 96), blk>>>(ao, mow, mob, x1, aop,
                                                   LN, 128, 128, nullptr, nullptr);
    gemm128<ACT_RELU, false><<<dim3(1, 96), blk>>>(aop, roww, rob, nullptr, ctx,
                                                   LN, 128, 128, nullptr, nullptr);
    qv_kernel<<<LL, blk>>>(ctx, qw, qb, out_q);

    (void)in_sizes; (void)n_in; (void)out_size;
}

// round 3
// speedup vs baseline: 4.0273x; 2.5022x over previous
#include <cuda_runtime.h>
#include <math.h>

// ---- problem dims ----
#define NB 48
#define NA 16
#define LL 768            // NB*NA
#define EMB 128
#define QKVW 384

// distinct-row layout: e-part rows 0..767 (=(b,i)), a-part rows 768..1535 (=(b,j))
// post-attention distinct rows: 0..767 e-part (slot k=0), 768 + (k-1)*96 + b*2 + c
#define MPOST 2240        // 2208 valid rows padded to 35*64

// output layout in d_out (floats): policy_flat | q_values | eo
#define OUT_POLICY 0
#define OUT_Q      24576
#define OUT_EO     25344

// ---- scratch ----
__device__ __align__(256) float g_H1[LL * 256];
__device__ __align__(256) float g_H2[LL * 128];
__device__ __align__(256) float g_eoea[1536 * 128];
__device__ __align__(256) float g_x1d[1536 * 128];
__device__ __align__(256) float g_qkvd[1536 * QKVW];
__device__ __align__(256) float g_aod[MPOST * 128];
__device__ __align__(256) float g_aopd[MPOST * 128];
__device__ __align__(256) float g_ctxd[MPOST * 128];
__device__ __align__(256) float g_qvd[MPOST];

#define ACT_NONE 0
#define ACT_LEAKY 1
#define ACT_GELU 2
#define ACT_RELU 3

// residual-gather map: post-row m -> x1d row
__device__ __forceinline__ int res_map(int m) {
    if (m < 768) return m;
    int t = m - 768;
    if (t >= 1440) return 0;            // pad rows: harmless
    int k = t / 96 + 1;
    int r = t % 96;
    int b = r >> 1, c = r & 1;
    int j = c ? (k - 1) : k;
    return 768 + b * 16 + j;
}

// ============================================================================
// gemm64db: 64x64x16, 4x4 micro, double-buffered.
//   CATA : A row = [obs(128) | policy(32)]  (K=160)
//   SPLIT: N=384, W=[aw1(256 rows)|eow(128 rows)], cols<256 -> leaky -> C
//          (stride 256); cols>=256 -> none -> C2 and C3 (stride 128)
//   RESG : add Res[res_map(m)][n] before activation
// ============================================================================
template <int ACTI, bool CATA, bool SPLIT, bool RESG>
__global__ void __launch_bounds__(256)
gemm64db(const float* __restrict__ A, const float* __restrict__ A2,
         const float* __restrict__ W, const float* __restrict__ W2,
         const float* __restrict__ bias, const float* __restrict__ bias2,
         const float* __restrict__ Res,
         float* __restrict__ C, float* __restrict__ C2, float* __restrict__ C3,
         int M, int N, int K)
{
    __shared__ __align__(16) float As[2][16][64];
    __shared__ __align__(16) float Ws[2][16][64];

    const int tid = threadIdx.x;
    const int tx = tid & 15;
    const int ty = tid >> 4;
    const int m0 = blockIdx.y * 64;
    const int n0 = blockIdx.x * 64;
    const int lr = tid >> 2;
    const int lc = (tid & 3) * 4;

    auto loadA = [&](int k0) -> float4 {
        const int k = k0 + lc;
        if (CATA) {
            const float* p = (k < 128) ? (A  + (size_t)(m0 + lr) * 128 + k)
                                       : (A2 + (size_t)(m0 + lr) * 32 + (k - 128));
            return *(const float4*)p;
        }
        return *(const float4*)(A + (size_t)(m0 + lr) * K + k);
    };
    auto loadW = [&](int k0) -> float4 {
        const int n = n0 + lr;
        if (SPLIT) {
            const float* p = (n < 256) ? (W  + (size_t)n * K + k0 + lc)
                                       : (W2 + (size_t)(n - 256) * K + k0 + lc);
            return *(const float4*)p;
        }
        if (n < N) return *(const float4*)(W + (size_t)n * K + k0 + lc);
        return make_float4(0.f, 0.f, 0.f, 0.f);
    };

    float acc[4][4];
#pragma unroll
    for (int i = 0; i < 4; i++)
#pragma unroll
        for (int j = 0; j < 4; j++) acc[i][j] = 0.f;

    float4 a_pre = loadA(0);
    float4 w_pre = loadW(0);
    As[0][lc + 0][lr] = a_pre.x; As[0][lc + 1][lr] = a_pre.y;
    As[0][lc + 2][lr] = a_pre.z; As[0][lc + 3][lr] = a_pre.w;
    Ws[0][lc + 0][lr] = w_pre.x; Ws[0][lc + 1][lr] = w_pre.y;
    Ws[0][lc + 2][lr] = w_pre.z; Ws[0][lc + 3][lr] = w_pre.w;
    __syncthreads();

    int buf = 0;
    for (int k0 = 0; k0 < K; k0 += 16) {
        const bool has_next = (k0 + 16 < K);
        if (has_next) { a_pre = loadA(k0 + 16); w_pre = loadW(k0 + 16); }
#pragma unroll
        for (int kk = 0; kk < 16; kk++) {
            float4 a = *(const float4*)&As[buf][kk][ty * 4];
            float4 b = *(const float4*)&Ws[buf][kk][tx * 4];
            acc[0][0] += a.x * b.x; acc[0][1] += a.x * b.y; acc[0][2] += a.x * b.z; acc[0][3] += a.x * b.w;
            acc[1][0] += a.y * b.x; acc[1][1] += a.y * b.y; acc[1][2] += a.y * b.z; acc[1][3] += a.y * b.w;
            acc[2][0] += a.z * b.x; acc[2][1] += a.z * b.y; acc[2][2] += a.z * b.z; acc[2][3] += a.z * b.w;
            acc[3][0] += a.w * b.x; acc[3][1] += a.w * b.y; acc[3][2] += a.w * b.z; acc[3][3] += a.w * b.w;
        }
        if (has_next) {
            const int nb = buf ^ 1;
            As[nb][lc + 0][lr] = a_pre.x; As[nb][lc + 1][lr] = a_pre.y;
            As[nb][lc + 2][lr] = a_pre.z; As[nb][lc + 3][lr] = a_pre.w;
            Ws[nb][lc + 0][lr] = w_pre.x; Ws[nb][lc + 1][lr] = w_pre.y;
            Ws[nb][lc + 2][lr] = w_pre.z; Ws[nb][lc + 3][lr] = w_pre.w;
            __syncthreads();
            buf = nb;
        }
    }

#pragma unroll
    for (int i = 0; i < 4; i++) {
        const int m = m0 + ty * 4 + i;
        const float* rres = nullptr;
        if (RESG) rres = Res + (size_t)res_map(m) * 128;
#pragma unroll
        for (int j = 0; j < 4; j++) {
            const int n = n0 + tx * 4 + j;
            if (SPLIT) {
                if (n < 256) {
                    float v = acc[i][j] + bias[n];
                    v = (v > 0.f) ? v : 0.01f * v;     // leaky for actor L1
                    C[(size_t)m * 256 + n] = v;
                } else {
                    float v = acc[i][j] + bias2[n - 256];
                    C2[(size_t)m * 128 + (n - 256)] = v;
                    C3[(size_t)m * 128 + (n - 256)] = v;
                }
            } else if (n < N) {
                float v = acc[i][j] + bias[n];
                if (RESG) v += rres[n];
                if (ACTI == ACT_LEAKY) v = (v > 0.f) ? v : 0.01f * v;
                else if (ACTI == ACT_GELU) v = 0.5f * v * (1.0f + erff(v * 0.70710678118654752f));
                else if (ACTI == ACT_RELU) v = fmaxf(v, 0.f);
                C[(size_t)m * N + n] = v;
            }
        }
    }
}

// ============================================================================
// flash64: full attention for slot k=0 (4 heads). l-tile 64, m loop over 768.
// qkvd rows 0..767 (e-part), stride 384. Writes aod rows 0..767.
// ============================================================================
struct Flash64Smem {
    float Qs[32][68];
    float Ks[32][68];
    float Vs[64][36];
    float Ss[64][68];
    float Pt[64][68];
    float Ms[64], Ls[64], Cs[64];
};

__global__ void __launch_bounds__(256)
flash64(const float* __restrict__ qkvd, float* __restrict__ aod)
{
    extern __shared__ char raw[];
    Flash64Smem& sm = *reinterpret_cast<Flash64Smem*>(raw);

    const int h = blockIdx.y;
    const int l0 = blockIdx.x * 64;
    const float* Qb = qkvd + h * 32;
    const float* Kb = qkvd + 128 + h * 32;
    const float* Vb = qkvd + 256 + h * 32;
    const int tid = threadIdx.x;

    // Q tile 64x32 transposed
#pragma unroll
    for (int t = 0; t < 2; t++) {
        const int f = tid + t * 256;
        const int r = f >> 3, c = (f & 7) * 4;
        float4 v = *(const float4*)(Qb + (size_t)(l0 + r) * QKVW + c);
        sm.Qs[c + 0][r] = v.x; sm.Qs[c + 1][r] = v.y;
        sm.Qs[c + 2][r] = v.z; sm.Qs[c + 3][r] = v.w;
    }
    if (tid < 64) { sm.Ms[tid] = -1e30f; sm.Ls[tid] = 0.f; }

    float O[2][4];
#pragma unroll
    for (int i = 0; i < 2; i++)
#pragma unroll
        for (int j = 0; j < 4; j++) O[i][j] = 0.f;

    const int txA = tid & 15, tyA = tid >> 4;
    const int rB = tid >> 2,  hB = tid & 3;
    const int txC = tid & 7,  tyC = tid >> 3;

    for (int m0 = 0; m0 < LL; m0 += 64) {
        __syncthreads();
#pragma unroll
        for (int t = 0; t < 2; t++) {
            const int f = tid + t * 256;
            const int r = f >> 3, c = (f & 7) * 4;
            float4 kv = *(const float4*)(Kb + (size_t)(m0 + r) * QKVW + c);
            sm.Ks[c + 0][r] = kv.x; sm.Ks[c + 1][r] = kv.y;
            sm.Ks[c + 2][r] = kv.z; sm.Ks[c + 3][r] = kv.w;
            float4 vv = *(const float4*)(Vb + (size_t)(m0 + r) * QKVW + c);
            *(float4*)&sm.Vs[r][c] = vv;
        }
        __syncthreads();

        // phase A: S = Q.K^T * scale
        float fa[4][4];
#pragma unroll
        for (int i = 0; i < 4; i++)
#pragma unroll
            for (int j = 0; j < 4; j++) fa[i][j] = 0.f;
#pragma unroll 8
        for (int d = 0; d < 32; d++) {
            float4 a = *(const float4*)&sm.Qs[d][tyA * 4];
            float4 b = *(const float4*)&sm.Ks[d][txA * 4];
            fa[0][0] += a.x * b.x; fa[0][1] += a.x * b.y; fa[0][2] += a.x * b.z; fa[0][3] += a.x * b.w;
            fa[1][0] += a.y * b.x; fa[1][1] += a.y * b.y; fa[1][2] += a.y * b.z; fa[1][3] += a.y * b.w;
            fa[2][0] += a.z * b.x; fa[2][1] += a.z * b.y; fa[2][2] += a.z * b.z; fa[2][3] += a.z * b.w;
            fa[3][0] += a.w * b.x; fa[3][1] += a.w * b.y; fa[3][2] += a.w * b.z; fa[3][3] += a.w * b.w;
        }
        const float sc = 0.17677669529663687f;
#pragma unroll
        for (int i = 0; i < 4; i++)
#pragma unroll
            for (int j = 0; j < 4; j++)
                sm.Ss[tyA * 4 + i][txA * 4 + j] = fa[i][j] * sc;
        __syncthreads();

        // phase B: online softmax (4 threads / row, 16 cols each)
        {
            const float* srow = &sm.Ss[rB][hB * 16];
            float mloc = -1e30f;
#pragma unroll
            for (int j = 0; j < 16; j++) mloc = fmaxf(mloc, srow[j]);
            mloc = fmaxf(mloc, __shfl_xor_sync(0xffffffffu, mloc, 1));
            mloc = fmaxf(mloc, __shfl_xor_sync(0xffffffffu, mloc, 2));
            float m_old = sm.Ms[rB];
            float m_new = fmaxf(m_old, mloc);
            float corr = __expf(m_old - m_new);
            float s = 0.f;
#pragma unroll
            for (int j = 0; j < 16; j++) {
                float e = __expf(srow[j] - m_new);
                sm.Pt[hB * 16 + j][rB] = e;
                s += e;
            }
            s += __shfl_xor_sync(0xffffffffu, s, 1);
            s += __shfl_xor_sync(0xffffffffu, s, 2);
            if (hB == 0) {
                sm.Ms[rB] = m_new;
                sm.Ls[rB] = sm.Ls[rB] * corr + s;
                sm.Cs[rB] = corr;
            }
        }
        __syncthreads();

        // phase C: O = O*corr + P.V   (2 rows x 4 cols per thread)
        const float c0 = sm.Cs[tyC * 2];
        const float c1 = sm.Cs[tyC * 2 + 1];
#pragma unroll
        for (int j = 0; j < 4; j++) { O[0][j] *= c0; O[1][j] *= c1; }
#pragma unroll 8
        for (int mm = 0; mm < 64; mm++) {
            const float a0 = sm.Pt[mm][tyC * 2];
            const float a1 = sm.Pt[mm][tyC * 2 + 1];
            float4 b = *(const float4*)&sm.Vs[mm][txC * 4];
            O[0][0] += a0 * b.x; O[0][1] += a0 * b.y; O[0][2] += a0 * b.z; O[0][3] += a0 * b.w;
            O[1][0] += a1 * b.x; O[1][1] += a1 * b.y; O[1][2] += a1 * b.z; O[1][3] += a1 * b.w;
        }
    }

#pragma unroll
    for (int i = 0; i < 2; i++) {
        const int l = l0 + tyC * 2 + i;
        const float inv = 1.0f / sm.Ls[tyC * 2 + i];
        float out[4];
#pragma unroll
        for (int j = 0; j < 4; j++) out[j] = O[i][j] * inv;
        *(float4*)(aod + (size_t)l * 128 + h * 32 + txC * 4) = *(float4*)&out[0];
    }
}

// ============================================================================
// cls_attn: slot k>=1 attention on 96 distinct (b, c) classes with
// multiplicity weights w(c'=0)=k, w(c'=1)=16-k. Exact.
// grid = 60 = (k-1) + 15*h
// ============================================================================
struct ClsSmem {
    float Qc[96][36];
    float Kc[96][36];
    float Vc[96][36];
    float Sc[96][97];
};

__global__ void __launch_bounds__(256)
cls_attn(const float* __restrict__ qkvd, float* __restrict__ aod)
{
    extern __shared__ char raw[];
    ClsSmem& sm = *reinterpret_cast<ClsSmem*>(raw);

    const int bx = blockIdx.x;
    const int k = bx % 15 + 1;
    const int h = bx / 15;
    const int tid = threadIdx.x;

    // load 96 class rows of Q/K/V (head h)
#pragma unroll
    for (int t = 0; t < 3; t++) {
        const int f = tid + t * 256;   // 0..767
        const int r = f >> 3, c = (f & 7) * 4;
        const int b = r >> 1, cc = r & 1;
        const int j = cc ? (k - 1) : k;
        const float* base = qkvd + (size_t)(768 + b * 16 + j) * QKVW + h * 32 + c;
        *(float4*)&sm.Qc[r][c] = *(const float4*)(base);
        *(float4*)&sm.Kc[r][c] = *(const float4*)(base + 128);
        *(float4*)&sm.Vc[r][c] = *(const float4*)(base + 256);
    }
    __syncthreads();

    // S = Q.K^T * scale : 6x6 micro over 96x96
    const int tx = tid & 15, ty = tid >> 4;
    {
        float acc[6][6];
#pragma unroll
        for (int i = 0; i < 6; i++)
#pragma unroll
            for (int j = 0; j < 6; j++) acc[i][j] = 0.f;
#pragma unroll 8
        for (int d = 0; d < 32; d++) {
            float a[6], b[6];
#pragma unroll
            for (int i = 0; i < 6; i++) a[i] = sm.Qc[ty * 6 + i][d];
#pragma unroll
            for (int j = 0; j < 6; j++) b[j] = sm.Kc[tx * 6 + j][d];
#pragma unroll
            for (int i = 0; i < 6; i++)
#pragma unroll
                for (int j = 0; j < 6; j++) acc[i][j] += a[i] * b[j];
        }
        const float scl = 0.17677669529663687f;
#pragma unroll
        for (int i = 0; i < 6; i++)
#pragma unroll
            for (int j = 0; j < 6; j++)
                sm.Sc[ty * 6 + i][tx * 6 + j] = acc[i][j] * scl;
    }
    __syncthreads();

    // weighted softmax per row (fold w and 1/denom into Sc)
    if (tid < 96) {
        float mx = -1e30f;
#pragma unroll 8
        for (int m = 0; m < 96; m++) mx = fmaxf(mx, sm.Sc[tid][m]);
        const float w0 = (float)k, w1 = (float)(16 - k);
        float s = 0.f;
#pragma unroll 8
        for (int m = 0; m < 96; m++) {
            float w = (m & 1) ? w1 : w0;
            float e = w * __expf(sm.Sc[tid][m] - mx);
            sm.Sc[tid][m] = e;
            s += e;
        }
        const float inv = 1.0f / s;
#pragma unroll 8
        for (int m = 0; m < 96; m++) sm.Sc[tid][m] *= inv;
    }
    __syncthreads();

    // O = P.V : 3 rows x 4 cols per thread
    const int txo = tid & 7, tyo = tid >> 3;
    float o[3][4];
#pragma unroll
    for (int i = 0; i < 3; i++)
#pragma unroll
        for (int j = 0; j < 4; j++) o[i][j] = 0.f;
#pragma unroll 8
    for (int m = 0; m < 96; m++) {
        float a[3];
#pragma unroll
        for (int i = 0; i < 3; i++) a[i] = sm.Sc[tyo * 3 + i][m];
        float4 b = *(const float4*)&sm.Vc[m][txo * 4];
#pragma unroll
        for (int i = 0; i < 3; i++) {
            o[i][0] += a[i] * b.x; o[i][1] += a[i] * b.y;
            o[i][2] += a[i] * b.z; o[i][3] += a[i] * b.w;
        }
    }
#pragma unroll
    for (int i = 0; i < 3; i++) {
        const int row = 768 + (k - 1) * 96 + tyo * 3 + i;
        *(float4*)(aod + (size_t)row * 128 + h * 32 + txo * 4) = *(float4*)&o[i][0];
    }
}

// ---- per-row q scalar: qvd[m] = ctx[m].qw + qb ----
__global__ void qv_rows(const float* __restrict__ ctx, const float* __restrict__ qw,
                        const float* __restrict__ qb, float* __restrict__ qvd)
{
    const int w = (blockIdx.x * blockDim.x + threadIdx.x) >> 5;
    const int lane = threadIdx.x & 31;
    if (w >= 2208) return;
    const float* r = ctx + (size_t)w * 128;
    float s = 0.f;
#pragma unroll
    for (int c = lane; c < 128; c += 32) s += r[c] * qw[c];
#pragma unroll
    for (int o = 16; o; o >>= 1) s += __shfl_xor_sync(0xffffffffu, s, o);
    if (!lane) qvd[w] = s + qb[0];
}

// ---- assemble q_values from class values ----
__global__ void assemble(const float* __restrict__ qvd, float* __restrict__ out_q)
{
    const int l = blockIdx.x * 256 + threadIdx.x;
    if (l >= 768) return;
    const int b = l >> 4, i = l & 15;
    float s = qvd[l];
#pragma unroll
    for (int k = 1; k < 16; k++) {
        const int c = (i < k) ? 0 : 1;
        s += qvd[768 + (k - 1) * 96 + b * 2 + c];
    }
    out_q[l] = s;
}

extern "C" void kernel_launch(void* const* d_in, const int* in_sizes, int n_in,
                              void* d_out, int out_size)
{
    const float* obs = (const float*)d_in[0];
    const float* aw1 = (const float*)d_in[1];  const float* ab1 = (const float*)d_in[2];
    const float* aw2 = (const float*)d_in[3];  const float* ab2 = (const float*)d_in[4];
    const float* aw3 = (const float*)d_in[5];  const float* ab3 = (const float*)d_in[6];
    const float* eow = (const float*)d_in[7];  const float* eob = (const float*)d_in[8];
    const float* eaw = (const float*)d_in[9];  const float* eab = (const float*)d_in[10];
    const float* riw = (const float*)d_in[11]; const float* rib = (const float*)d_in[12];
    const float* roww = (const float*)d_in[13]; const float* rob = (const float*)d_in[14];
    const float* miw = (const float*)d_in[15]; const float* mib = (const float*)d_in[16];
    const float* mow = (const float*)d_in[17]; const float* mob = (const float*)d_in[18];
    const float* qw  = (const float*)d_in[19]; const float* qb  = (const float*)d_in[20];

    float* out = (float*)d_out;
    float* out_policy = out + OUT_POLICY;
    float* out_q      = out + OUT_Q;
    float* out_eo     = out + OUT_EO;

    float *H1, *H2, *eoea, *x1d, *qkvd, *aod, *aopd, *ctxd, *qvd;
    cudaGetSymbolAddress((void**)&H1, g_H1);
    cudaGetSymbolAddress((void**)&H2, g_H2);
    cudaGetSymbolAddress((void**)&eoea, g_eoea);
    cudaGetSymbolAddress((void**)&x1d, g_x1d);
    cudaGetSymbolAddress((void**)&qkvd, g_qkvd);
    cudaGetSymbolAddress((void**)&aod, g_aod);
    cudaGetSymbolAddress((void**)&aopd, g_aopd);
    cudaGetSymbolAddress((void**)&ctxd, g_ctxd);
    cudaGetSymbolAddress((void**)&qvd, g_qvd);

    cudaFuncSetAttribute(flash64, cudaFuncAttributeMaxDynamicSharedMemorySize,
                         (int)sizeof(Flash64Smem));
    cudaFuncSetAttribute(cls_attn, cudaFuncAttributeMaxDynamicSharedMemorySize,
                         (int)sizeof(ClsSmem));

    dim3 blk(256);

    // G1: obs @ [aw1 | eow]  ->  H1 (leaky, stride 256) + eo (none, dual write)
    gemm64db<ACT_NONE, false, true, false><<<dim3(6, 12), blk>>>(
        obs, nullptr, aw1, eow, ab1, eob, nullptr, H1, out_eo, eoea, LL, 384, 128);
    // G2: actor hidden 2
    gemm64db<ACT_LEAKY, false, false, false><<<dim3(2, 12), blk>>>(
        H1, nullptr, aw2, nullptr, ab2, nullptr, nullptr, H2, nullptr, nullptr, LL, 128, 256);
    // G3: policy (exact GELU)
    gemm64db<ACT_GELU, false, false, false><<<dim3(1, 12), blk>>>(
        H2, nullptr, aw3, nullptr, ab3, nullptr, nullptr, out_policy, nullptr, nullptr, LL, 32, 128);
    // G4: ea = [obs|policy] @ eaw   (cat fused in loader)
    gemm64db<ACT_NONE, true, false, false><<<dim3(2, 12), blk>>>(
        obs, out_policy, eaw, nullptr, eab, nullptr, nullptr, eoea + 768 * 128,
        nullptr, nullptr, LL, 128, 160);
    // G5: x1 distinct rows = relu([eo;ea] @ riw)
    gemm64db<ACT_RELU, false, false, false><<<dim3(2, 24), blk>>>(
        eoea, nullptr, riw, nullptr, rib, nullptr, nullptr, x1d, nullptr, nullptr, 1536, 128, 128);
    // G6: qkv distinct rows
    gemm64db<ACT_NONE, false, false, false><<<dim3(6, 24), blk>>>(
        x1d, nullptr, miw, nullptr, mib, nullptr, nullptr, qkvd, nullptr, nullptr, 1536, 384, 128);

    // attention
    flash64<<<dim3(12, 4), blk, sizeof(Flash64Smem)>>>(qkvd, aod);
    cls_attn<<<60, blk, sizeof(ClsSmem)>>>(qkvd, aod);

    // G7: out_proj + gathered residual
    gemm64db<ACT_NONE, false, false, true><<<dim3(2, 35), blk>>>(
        aod, nullptr, mow, nullptr, mob, nullptr, x1d, aopd, nullptr, nullptr, MPOST, 128, 128);
    // G8: output layer (relu)
    gemm64db<ACT_RELU, false, false, false><<<dim3(2, 35), blk>>>(
        aopd, nullptr, roww, nullptr, rob, nullptr, nullptr, ctxd, nullptr, nullptr, MPOST, 128, 128);

    // q head + assembly
    qv_rows<<<(2208 * 32 + 255) / 256, blk>>>(ctxd, qw, qb, qvd);
    assemble<<<3, blk>>>(qvd, out_q);

    (void)in_sizes; (void)n_in; (void)out_size;
}